// round 4
// baseline (speedup 1.0000x reference)
#include <cuda_runtime.h>
#include <cstdint>

#define OUT_F 16

// ---------------------------------------------------------------------------
// Kernel 1: zero the output (harness poisons d_out with 0xAA).
// ---------------------------------------------------------------------------
__global__ void __launch_bounds__(256)
zero_out_kernel(float4* __restrict__ out, int n4) {
    int stride = gridDim.x * blockDim.x;
    for (int i = blockIdx.x * blockDim.x + threadIdx.x; i < n4; i += stride)
        out[i] = make_float4(0.f, 0.f, 0.f, 0.f);
}

// ---------------------------------------------------------------------------
// Kernel 2: scatter-add, warp-cooperative quad layout.
// Each warp processes 8 edges per iteration:
//   - lanes 0..7 issue ONE coalesced 32B load of src[e_base..e_base+7]
//     (1 LDG per warp instead of 32 redundant ones), distributed to all
//     lanes via __shfl_sync (lane>>2)
//   - lane t loads w[e_base*4 + t]  -> perfectly coalesced 512B per warp
//   - each lane issues one red.global.add.v4.f32 to its edge's output row
//     chunk; 4 adjacent lanes cover one contiguous 64B row
// LSU ops/edge: 1.03 LDG + 1 RED (was 2 LDG + 1 RED).
// ---------------------------------------------------------------------------
__global__ void __launch_bounds__(256)
scatter_add_warp8(const int* __restrict__ src,
                  const float4* __restrict__ w,    // edge_w as [E*4] float4
                  float* __restrict__ out,         // [N][16]
                  int E)
{
    const int lane   = threadIdx.x & 31;
    const int gwarp  = (blockIdx.x * blockDim.x + threadIdx.x) >> 5;
    const int nwarps = (gridDim.x * blockDim.x) >> 5;
    const int chunk  = lane & 3;      // which float4 of the row
    const int sub    = lane >> 2;     // which of the warp's 8 edges

    for (int e_base = gwarp * 8; e_base < E; e_base += nwarps * 8) {
        // one coalesced 32B index load for 8 edges
        int sv = 0;
        if (lane < 8 && (e_base + lane) < E)
            sv = __ldg(src + e_base + lane);
        int s = __shfl_sync(0xffffffffu, sv, sub);

        int e = e_base + sub;
        if (e < E) {
            // w[e*4 + chunk] == w[e_base*4 + lane]  (coalesced)
            float4 v = __ldcs(w + (size_t)e_base * 4 + lane);

            float* dst = out + (size_t)s * OUT_F + chunk * 4;
            asm volatile("red.global.add.v4.f32 [%0], {%1,%2,%3,%4};"
                         :: "l"(dst), "f"(v.x), "f"(v.y), "f"(v.z), "f"(v.w)
                         : "memory");
        }
    }
}

// ---------------------------------------------------------------------------
// kernel_launch
// Inputs (metadata order): edge [2, E] int32, edge_w [E, 16] f32, N, E, F
// ---------------------------------------------------------------------------
extern "C" void kernel_launch(void* const* d_in, const int* in_sizes, int n_in,
                              void* d_out, int out_size) {
    const int*    edge   = (const int*)d_in[0];      // [2, E]; row 0 = src
    const float4* edge_w = (const float4*)d_in[1];   // [E, 16] -> [4E] float4
    float*        out    = (float*)d_out;            // [N, 16]

    const int E  = in_sizes[0] / 2;                  // edge has 2*E elements
    const int n4 = out_size / 4;                     // output float4 count

    {
        int threads = 256;
        int blocks = (n4 + threads - 1) / threads;
        if (blocks > 8192) blocks = 8192;
        zero_out_kernel<<<blocks, threads>>>((float4*)out, n4);
    }
    {
        // one warp per 8 edges, single pass (no grid-stride wrap at this size)
        int threads = 256;
        long long warps_needed = ((long long)E + 7) / 8;
        long long blocks_ll = (warps_needed * 32 + threads - 1) / threads;
        int blocks = (blocks_ll > 1000000) ? 1000000 : (int)blocks_ll;  // 50000 for E=3.2M
        scatter_add_warp8<<<blocks, threads>>>(edge, edge_w, out, E);
    }
}

// round 6
// speedup vs baseline: 1.2946x; 1.2946x over previous
#include <cuda_runtime.h>
#include <cstdint>

#define OUT_F 16

// ---------------------------------------------------------------------------
// Kernel 1: zero the output (harness poisons d_out with 0xAA).
// ---------------------------------------------------------------------------
__global__ void __launch_bounds__(256)
zero_out_kernel(float4* __restrict__ out, int n4) {
    int stride = gridDim.x * blockDim.x;
    for (int i = blockIdx.x * blockDim.x + threadIdx.x; i < n4; i += stride)
        out[i] = make_float4(0.f, 0.f, 0.f, 0.f);
}

// ---------------------------------------------------------------------------
// Kernel 2: scatter-add, quad layout (4 threads per edge, one float4 chunk
// each) with 2-way ILP: each thread handles quad-elements t and t+half,
// issuing all 4 loads before the 2 REDs so four memory ops are in flight.
// Both element streams are fully coalesced (half is a multiple of 32).
// Each edge's 4 RED lanes are contiguous 64B -> LTS merges internally.
// ---------------------------------------------------------------------------
__global__ void __launch_bounds__(256)
scatter_add_quad2(const int* __restrict__ src,
                  const float4* __restrict__ w,    // edge_w as [4E] float4
                  float* __restrict__ out,         // [N][16]
                  int work,                        // 4*E
                  int half)                        // >= work/2, multiple of 32
{
    int t = blockIdx.x * blockDim.x + threadIdx.x;
    if (t >= half) return;

    int t2 = t + half;
    bool p2 = (t2 < work);

    // element 1
    int e1 = t >> 2, c1 = t & 3;
    int s1 = __ldg(src + e1);
    float4 v1 = __ldcs(w + t);

    // element 2
    int e2 = t2 >> 2, c2 = t2 & 3;
    int s2 = p2 ? __ldg(src + e2) : 0;
    float4 v2 = p2 ? __ldcs(w + t2) : make_float4(0.f, 0.f, 0.f, 0.f);

    float* dst1 = out + (size_t)s1 * OUT_F + c1 * 4;
    asm volatile("red.global.add.v4.f32 [%0], {%1,%2,%3,%4};"
                 :: "l"(dst1), "f"(v1.x), "f"(v1.y), "f"(v1.z), "f"(v1.w)
                 : "memory");

    if (p2) {
        float* dst2 = out + (size_t)s2 * OUT_F + c2 * 4;
        asm volatile("red.global.add.v4.f32 [%0], {%1,%2,%3,%4};"
                     :: "l"(dst2), "f"(v2.x), "f"(v2.y), "f"(v2.z), "f"(v2.w)
                     : "memory");
    }
}

// ---------------------------------------------------------------------------
// kernel_launch
// Inputs (metadata order): edge [2, E] int32, edge_w [E, 16] f32, N, E, F
// ---------------------------------------------------------------------------
extern "C" void kernel_launch(void* const* d_in, const int* in_sizes, int n_in,
                              void* d_out, int out_size) {
    const int*    edge   = (const int*)d_in[0];      // [2, E]; row 0 = src
    const float4* edge_w = (const float4*)d_in[1];   // [E, 16] -> [4E] float4
    float*        out    = (float*)d_out;            // [N, 16]

    const int E    = in_sizes[0] / 2;                // edge has 2*E elements
    const int work = 4 * E;                          // quad elements
    const int n4   = out_size / 4;                   // output float4 count

    int half = (work + 1) / 2;
    half = (half + 31) & ~31;                        // warp-aligned 2nd stream

    {
        int threads = 256;
        int blocks = (n4 + threads - 1) / threads;
        if (blocks > 8192) blocks = 8192;
        zero_out_kernel<<<blocks, threads>>>((float4*)out, n4);
    }
    {
        int threads = 256;
        int blocks = (half + threads - 1) / threads;   // 25000 for E=3.2M
        scatter_add_quad2<<<blocks, threads>>>(edge, edge_w, out, work, half);
    }
}

// round 7
// speedup vs baseline: 1.3170x; 1.0173x over previous
#include <cuda_runtime.h>
#include <cstdint>

#define OUT_F 16

// ---------------------------------------------------------------------------
// Scatter-add, quad layout (4 threads per edge, one float4 chunk each) with
// 4-way ILP: each thread handles quad-elements t, t+q, t+2q, t+3q, issuing
// all 8 loads before the 4 REDs so eight memory ops are in flight.
// All four element streams are fully coalesced (q is a multiple of 32).
// Each edge's 4 RED lanes form one contiguous 64B group -> LTS merges.
// ---------------------------------------------------------------------------
__global__ void __launch_bounds__(256)
scatter_add_quad4(const int* __restrict__ src,
                  const float4* __restrict__ w,    // edge_w as [4E] float4
                  float* __restrict__ out,         // [N][16]
                  int work,                        // 4*E
                  int q)                           // >= work/4, multiple of 32
{
    int t0 = blockIdx.x * blockDim.x + threadIdx.x;
    if (t0 >= q) return;

    int t1 = t0 + q;
    int t2 = t0 + 2 * q;
    int t3 = t0 + 3 * q;
    bool p1 = (t1 < work), p2 = (t2 < work), p3 = (t3 < work);

    // ---- issue all loads first (8 in flight) ----
    int s0 = __ldg(src + (t0 >> 2));
    int s1 = p1 ? __ldg(src + (t1 >> 2)) : 0;
    int s2 = p2 ? __ldg(src + (t2 >> 2)) : 0;
    int s3 = p3 ? __ldg(src + (t3 >> 2)) : 0;

    float4 v0 = __ldcs(w + t0);
    float4 v1 = p1 ? __ldcs(w + t1) : make_float4(0.f,0.f,0.f,0.f);
    float4 v2 = p2 ? __ldcs(w + t2) : make_float4(0.f,0.f,0.f,0.f);
    float4 v3 = p3 ? __ldcs(w + t3) : make_float4(0.f,0.f,0.f,0.f);

    // ---- reductions ----
    float* d0 = out + (size_t)s0 * OUT_F + (t0 & 3) * 4;
    asm volatile("red.global.add.v4.f32 [%0], {%1,%2,%3,%4};"
                 :: "l"(d0), "f"(v0.x), "f"(v0.y), "f"(v0.z), "f"(v0.w) : "memory");
    if (p1) {
        float* d1 = out + (size_t)s1 * OUT_F + (t1 & 3) * 4;
        asm volatile("red.global.add.v4.f32 [%0], {%1,%2,%3,%4};"
                     :: "l"(d1), "f"(v1.x), "f"(v1.y), "f"(v1.z), "f"(v1.w) : "memory");
    }
    if (p2) {
        float* d2 = out + (size_t)s2 * OUT_F + (t2 & 3) * 4;
        asm volatile("red.global.add.v4.f32 [%0], {%1,%2,%3,%4};"
                     :: "l"(d2), "f"(v2.x), "f"(v2.y), "f"(v2.z), "f"(v2.w) : "memory");
    }
    if (p3) {
        float* d3 = out + (size_t)s3 * OUT_F + (t3 & 3) * 4;
        asm volatile("red.global.add.v4.f32 [%0], {%1,%2,%3,%4};"
                     :: "l"(d3), "f"(v3.x), "f"(v3.y), "f"(v3.z), "f"(v3.w) : "memory");
    }
}

// ---------------------------------------------------------------------------
// kernel_launch
// Inputs (metadata order): edge [2, E] int32, edge_w [E, 16] f32, N, E, F
// ---------------------------------------------------------------------------
extern "C" void kernel_launch(void* const* d_in, const int* in_sizes, int n_in,
                              void* d_out, int out_size) {
    const int*    edge   = (const int*)d_in[0];      // [2, E]; row 0 = src
    const float4* edge_w = (const float4*)d_in[1];   // [E, 16] -> [4E] float4
    float*        out    = (float*)d_out;            // [N, 16]

    const int E    = in_sizes[0] / 2;                // edge has 2*E elements
    const int work = 4 * E;                          // quad elements

    int q = (work + 3) / 4;
    q = (q + 31) & ~31;                              // warp-aligned streams

    // zero output via memset node (cheaper than a kernel launch in the graph)
    cudaMemsetAsync(d_out, 0, (size_t)out_size * sizeof(float));

    {
        int threads = 256;
        int blocks = (q + threads - 1) / threads;    // 12500 for E=3.2M
        scatter_add_quad4<<<blocks, threads>>>(edge, edge_w, out, work, q);
    }
}